// round 7
// baseline (speedup 1.0000x reference)
#include <cuda_runtime.h>

#define NBLK 128
#define BE 128

#define SROW(r) ((r)*128 + ((r)>>2)*4)     // padded stage row offset (floats)

#define WB_F   6544
#define STG_OFF WB_F                       // stage rows 0..147
#define XROW   0                           // rows 0..19  (4 lat + 16 var)
#define H1ROW  20                          // rows 20..83
#define H2ROW  84                          // rows 84..147 (z staged in 84..91)
#define STG_F  19092                       // SROW(148) = 148*128+37*4
#define WST_OFF (STG_OFF + STG_F)          // 16 x 128 selected latent outputs
#define SM_F   (WST_OFF - 0 + 16*128 + WB_F - WB_F)  // see below
#define SMEM_FLOATS (WB_F + STG_F + 16*128)          // 27684
#define SMEM_BYTES (SMEM_FLOATS*4)                   // 110736 -> 2 CTAs/SM

typedef unsigned long long ull;

__device__ __forceinline__ ull bcast2(float x){ ull r; unsigned u=__float_as_uint(x);
  asm("mov.b64 %0,{%1,%1};":"=l"(r):"r"(u)); return r; }
__device__ __forceinline__ void fma2(ull &a, ull x, ull w){
  asm("fma.rn.f32x2 %0,%1,%2,%0;":"+l"(a):"l"(x),"l"(w)); }
__device__ __forceinline__ float2 unpk(ull a){ unsigned x,y;
  asm("mov.b64 {%0,%1},%2;":"=r"(x),"=r"(y):"l"(a));
  return make_float2(__uint_as_float(x),__uint_as_float(y)); }

__device__ __forceinline__ void cp16(float* dst, const float* __restrict__ src, int n, int tid){
  float4* d=(float4*)dst; const float4* s=(const float4*)src;
  for(int i=tid;i<(n>>2);i+=NBLK) d[i]=s[i];
}

// IN inputs (stage rows R0..) -> 64 relu outputs (stage rows ORow..).
// Lane owns outs {og*4..og*4+3} U {32+og*4..+3} for 8 elements e8..e8+7.
template<int IN, int R0, int ORow>
__device__ __forceinline__ void layer64(float* __restrict__ stg,
                                        const float* __restrict__ W,     // stride 64
                                        const float* __restrict__ bias,
                                        int og, int e8){
  ull acc[4][8];
  {
    const ull* bA=(const ull*)(bias + og*4);
    const ull* bB=(const ull*)(bias + 32 + og*4);
    ull b0=bA[0], b1=bA[1], b2=bB[0], b3=bB[1];
#pragma unroll
    for(int e=0;e<8;e++){acc[0][e]=b0;acc[1][e]=b1;acc[2][e]=b2;acc[3][e]=b3;}
  }
  const float* wA=W + og*4;
  const float* wB=W + 32 + og*4;
#pragma unroll 4
  for(int i=0;i<IN;i++){
    const float* xr = stg + SROW(R0+i) + e8;
    float4 ha=*(const float4*)(xr);
    float4 hb=*(const float4*)(xr+4);
    ulonglong2 wa=*(const ulonglong2*)(wA + i*64);
    ulonglong2 wc=*(const ulonglong2*)(wB + i*64);
    ull x[8]={bcast2(ha.x),bcast2(ha.y),bcast2(ha.z),bcast2(ha.w),
              bcast2(hb.x),bcast2(hb.y),bcast2(hb.z),bcast2(hb.w)};
#pragma unroll
    for(int e=0;e<8;e++){
      fma2(acc[0][e],x[e],wa.x); fma2(acc[1][e],x[e],wa.y);
      fma2(acc[2][e],x[e],wc.x); fma2(acc[3][e],x[e],wc.y);
    }
  }
#pragma unroll
  for(int c=0;c<2;c++){
#pragma unroll
    for(int p=0;p<2;p++){
      int pi=c*2+p;
      int r = ORow + c*32 + og*4 + 2*p;
      float lo[8], hi[8];
#pragma unroll
      for(int e=0;e<8;e++){
        float2 f=unpk(acc[pi][e]);
        lo[e]=fmaxf(f.x,0.f); hi[e]=fmaxf(f.y,0.f);
      }
      float* o0 = stg + SROW(r) + e8;
      float* o1 = stg + SROW(r+1) + e8;
      *(float4*)(o0)   = make_float4(lo[0],lo[1],lo[2],lo[3]);
      *(float4*)(o0+4) = make_float4(lo[4],lo[5],lo[6],lo[7]);
      *(float4*)(o1)   = make_float4(hi[0],hi[1],hi[2],hi[3]);
      *(float4*)(o1+4) = make_float4(hi[4],hi[5],hi[6],hi[7]);
    }
  }
}

__global__ __launch_bounds__(NBLK,2)
void gen_kernel(const float *__restrict__ z, const float *__restrict__ data,
                const float *__restrict__ glog, const float *__restrict__ glat,
                const float *__restrict__ gbin,
                const float *__restrict__ LW0, const float *__restrict__ Lb0,
                const float *__restrict__ LW1, const float *__restrict__ Lb1,
                const float *__restrict__ LW2, const float *__restrict__ Lb2,
                const float *__restrict__ NW0, const float *__restrict__ Nb0,
                const float *__restrict__ NW1, const float *__restrict__ Nb1,
                const float *__restrict__ NWf, const float *__restrict__ Nbf,
                const float *__restrict__ W7f, const float *__restrict__ b7f,
                float *__restrict__ out) {
  extern __shared__ float sm[];
  float* wb  = sm;
  float* STG = sm + STG_OFF;
  float* WST = sm + WST_OFF;
  const int tid=threadIdx.x;
  const int w=tid>>5, lane=tid&31;
  const int og=lane&7, eg=lane>>3;
  const int e8=w*32+eg*8;               // main-layer element offset
  const int base=blockIdx.x*BE;

  __shared__ int ksel[4];
  if(tid<4){
    const float* a=glog+tid*8; const float* g=glat+tid*8;
    float best=a[0]+g[0]; int bi=0;
#pragma unroll
    for(int k=1;k<8;k++){ float v=a[k]+g[k]; if(v>best){best=v;bi=k;} } // first-max wins
    ksel[tid]=bi;
  }

  // data passthrough (cols 0..31) + var0 -> X rows 4..19 ; thread = element
  {
    int el=base+tid;
    const float* dr=data+(size_t)el*113;
    float* orw=out+(size_t)el*113;
#pragma unroll
    for(int c=0;c<16;c++){
      float v=dr[c]; orw[c]=v;
      STG[SROW(XROW+4+c)+tid]=v;
    }
#pragma unroll
    for(int c=16;c<32;c++) orw[c]=dr[c];
  }
  __syncthreads();

  // ================= latent phase =================
#pragma unroll 1
  for(int l=0;l<4;l++){
    cp16(wb,      LW0+(size_t)l*512, 512, tid);
    cp16(wb+512,  Lb0+l*64,           64, tid);
    cp16(wb+576,  LW1+(size_t)l*4096,4096,tid);
    cp16(wb+4672, Lb1+l*64,           64, tid);
    {
      int k=ksel[l];
      for(int i=tid;i<64;i+=NBLK)
        *(float4*)(wb+4736+4*i)=*(const float4*)(LW2+((size_t)(l*64+i))*32+k*4);
      if(tid<4) wb[4992+tid]=Lb2[l*32+ksel[l]*4+tid];
    }
    { // z -> H2 rows 0..7 (feature-major); thread = element
      float4 a=*(const float4*)(z+(size_t)(base+tid)*32+l*8);
      float4 b=*(const float4*)(z+(size_t)(base+tid)*32+l*8+4);
      STG[SROW(H2ROW+0)+tid]=a.x; STG[SROW(H2ROW+1)+tid]=a.y;
      STG[SROW(H2ROW+2)+tid]=a.z; STG[SROW(H2ROW+3)+tid]=a.w;
      STG[SROW(H2ROW+4)+tid]=b.x; STG[SROW(H2ROW+5)+tid]=b.y;
      STG[SROW(H2ROW+6)+tid]=b.z; STG[SROW(H2ROW+7)+tid]=b.w;
    }
    __syncthreads();
    layer64<8,  H2ROW, H1ROW>(STG, wb,     wb+512,  og, e8);
    __syncthreads();
    layer64<64, H1ROW, H2ROW>(STG, wb+576, wb+4672, og, e8);
    __syncthreads();
    { // latent final 64->4 selected (no relu)
      int eg4=lane&3, ef=w*32+eg4*8;
      ull acc[2][8];
      { const ull* bb=(const ull*)(wb+4992);
        ull b0=bb[0], b1=bb[1];
#pragma unroll
        for(int e=0;e<8;e++){acc[0][e]=b0;acc[1][e]=b1;} }
#pragma unroll 4
      for(int i=0;i<64;i++){
        const float* xr=STG+SROW(H2ROW+i)+ef;
        float4 ha=*(const float4*)(xr);
        float4 hb=*(const float4*)(xr+4);
        ulonglong2 wv=*(const ulonglong2*)(wb+4736+i*4);
        ull x[8]={bcast2(ha.x),bcast2(ha.y),bcast2(ha.z),bcast2(ha.w),
                  bcast2(hb.x),bcast2(hb.y),bcast2(hb.z),bcast2(hb.w)};
#pragma unroll
        for(int e=0;e<8;e++){ fma2(acc[0][e],x[e],wv.x); fma2(acc[1][e],x[e],wv.y); }
      }
      if(lane<4){
        float q0[8],q1[8],q2[8],q3[8];
#pragma unroll
        for(int e=0;e<8;e++){
          float2 f0=unpk(acc[0][e]), f1=unpk(acc[1][e]);
          q0[e]=f0.x; q1[e]=f0.y; q2[e]=f1.x; q3[e]=f1.y;
        }
        float* w0=WST+(l*4+0)*128+ef; float* w1=WST+(l*4+1)*128+ef;
        float* w2=WST+(l*4+2)*128+ef; float* w3=WST+(l*4+3)*128+ef;
        *(float4*)(w0)=make_float4(q0[0],q0[1],q0[2],q0[3]); *(float4*)(w0+4)=make_float4(q0[4],q0[5],q0[6],q0[7]);
        *(float4*)(w1)=make_float4(q1[0],q1[1],q1[2],q1[3]); *(float4*)(w1+4)=make_float4(q1[4],q1[5],q1[6],q1[7]);
        *(float4*)(w2)=make_float4(q2[0],q2[1],q2[2],q2[3]); *(float4*)(w2+4)=make_float4(q2[4],q2[5],q2[6],q2[7]);
        *(float4*)(w3)=make_float4(q3[0],q3[1],q3[2],q3[3]); *(float4*)(w3+4)=make_float4(q3[4],q3[5],q3[6],q3[7]);
      }
    }
    __syncthreads();
  }

  // ================= node chain =================
  const int LAY[6]={0,1,2,3,0,1};   // PARENT_LAT - 1
#pragma unroll 1
  for(int j=0;j<6;j++){
    cp16(wb,      NW0+(size_t)j*1280,1280,tid);
    cp16(wb+1280, Nb0+j*64,           64, tid);
    cp16(wb+1344, NW1+(size_t)j*4096,4096,tid);
    cp16(wb+5440, Nb1+j*64,           64, tid);
    if(j<5){ cp16(wb+5504, NWf+(size_t)j*1024,1024,tid); cp16(wb+6528, Nbf+j*16,16,tid); }
    else   { cp16(wb+5504, W7f,128,tid); if(tid<2) wb[6528+tid]=b7f[tid]; }
    { // lat features -> X rows 0..3 ; thread = element
      const float* src=WST+LAY[j]*4*128+tid;
      STG[SROW(XROW+0)+tid]=src[0];
      STG[SROW(XROW+1)+tid]=src[128];
      STG[SROW(XROW+2)+tid]=src[256];
      STG[SROW(XROW+3)+tid]=src[384];
    }
    __syncthreads();
    layer64<20, XROW,  H1ROW>(STG, wb,      wb+1280, og, e8);
    __syncthreads();
    layer64<64, H1ROW, H2ROW>(STG, wb+1344, wb+5440, og, e8);
    __syncthreads();
    if(j<5){
      // node final 64->16 (no relu): lane: og2 owns outs og2*4..+3, eg8 owns 4 elems
      int og2=lane&3, eg8=lane>>2, e4=w*32+eg8*4;
      ull acc[2][4];
      { const ull* bb=(const ull*)(wb+6528+og2*4);
        ull b0=bb[0], b1=bb[1];
#pragma unroll
        for(int e=0;e<4;e++){acc[0][e]=b0;acc[1][e]=b1;} }
#pragma unroll 4
      for(int i=0;i<64;i++){
        float4 h=*(const float4*)(STG+SROW(H2ROW+i)+e4);
        ulonglong2 wv=*(const ulonglong2*)(wb+5504+i*16+og2*4);
        ull x[4]={bcast2(h.x),bcast2(h.y),bcast2(h.z),bcast2(h.w)};
#pragma unroll
        for(int e=0;e<4;e++){ fma2(acc[0][e],x[e],wv.x); fma2(acc[1][e],x[e],wv.y); }
      }
      float v[4][4];
#pragma unroll
      for(int e=0;e<4;e++){
        float2 f0=unpk(acc[0][e]), f1=unpk(acc[1][e]);
        v[0][e]=f0.x; v[1][e]=f0.y; v[2][e]=f1.x; v[3][e]=f1.y;
      }
      int node=j+2;
#pragma unroll
      for(int q=0;q<4;q++){
        int o=og2*4+q;
        *(float4*)(STG+SROW(XROW+4+o)+e4)=make_float4(v[q][0],v[q][1],v[q][2],v[q][3]);
#pragma unroll
        for(int e=0;e<4;e++)
          out[(size_t)(base+e4+e)*113 + 16*node + o]=v[q][e];
      }
    } else {
      // node 7: 64->2 logits, sigmoid + gumbel hard argmax -> col 112
      int eg4=lane&3, ef=w*32+eg4*8;
      ull acc[8];
      { ull b=((const ull*)(wb+6528))[0];
#pragma unroll
        for(int e=0;e<8;e++) acc[e]=b; }
#pragma unroll 4
      for(int i=0;i<64;i++){
        const float* xr=STG+SROW(H2ROW+i)+ef;
        float4 ha=*(const float4*)(xr);
        float4 hb=*(const float4*)(xr+4);
        ull wv=*(const ull*)(wb+5504+i*2);
        fma2(acc[0],bcast2(ha.x),wv); fma2(acc[1],bcast2(ha.y),wv);
        fma2(acc[2],bcast2(ha.z),wv); fma2(acc[3],bcast2(ha.w),wv);
        fma2(acc[4],bcast2(hb.x),wv); fma2(acc[5],bcast2(hb.y),wv);
        fma2(acc[6],bcast2(hb.z),wv); fma2(acc[7],bcast2(hb.w),wv);
      }
      if(lane<4){
#pragma unroll
        for(int e=0;e<8;e++){
          float2 f=unpk(acc[e]);
          float p0=1.f/(1.f+expf(-f.x));
          float p1=1.f/(1.f+expf(-f.y));
          int el=base+ef+e;
          float g0=gbin[(size_t)el*2], g1=gbin[(size_t)el*2+1];
          out[(size_t)el*113+112]=(p0+g0>=p1+g1)?1.f:0.f;   // first-index wins ties
        }
      }
    }
    __syncthreads();
  }
}

extern "C" void kernel_launch(void *const *d_in, const int *in_sizes, int n_in,
                              void *d_out, int out_size) {
  (void)in_sizes; (void)n_in; (void)out_size;
  const float *z    = (const float *)d_in[0];
  const float *data = (const float *)d_in[1];
  const float *glog = (const float *)d_in[2];
  const float *glat = (const float *)d_in[3];
  const float *gbin = (const float *)d_in[4];
  const float *LW0  = (const float *)d_in[5];
  const float *Lb0  = (const float *)d_in[6];
  const float *LW1  = (const float *)d_in[7];
  const float *Lb1  = (const float *)d_in[8];
  const float *LW2  = (const float *)d_in[9];
  const float *Lb2  = (const float *)d_in[10];
  const float *NW0  = (const float *)d_in[11];
  const float *Nb0  = (const float *)d_in[12];
  const float *NW1  = (const float *)d_in[13];
  const float *Nb1  = (const float *)d_in[14];
  const float *NWf  = (const float *)d_in[15];
  const float *Nbf  = (const float *)d_in[16];
  const float *W7f  = (const float *)d_in[17];
  const float *b7f  = (const float *)d_in[18];
  float *out = (float *)d_out;

  cudaFuncSetAttribute(gen_kernel, cudaFuncAttributeMaxDynamicSharedMemorySize, SMEM_BYTES);
  gen_kernel<<<131072/BE, NBLK, SMEM_BYTES>>>(
      z, data, glog, glat, gbin, LW0, Lb0, LW1, Lb1, LW2, Lb2,
      NW0, Nb0, NW1, Nb1, NWf, Nbf, W7f, b7f, out);
}

// round 9
// speedup vs baseline: 1.0690x; 1.0690x over previous
#include <cuda_runtime.h>

#define NBLK 128
#define BE 128

#define SROW(r) ((r)*128 + ((r)>>2)*4)     // padded stage row offset (floats)

#define WB_F   6544
#define STG_OFF WB_F                       // stage rows 0..147
#define XROW   0                           // rows 0..19  (4 lat + 16 var)
#define H1ROW  20                          // rows 20..83
#define H2ROW  84                          // rows 84..147 (z staged in 84..91)
#define STG_F  19092                       // SROW(148)
#define WST_OFF (STG_OFF + STG_F)          // 16 x 128 selected latent outputs
#define SMEM_FLOATS (WB_F + STG_F + 16*128)
#define SMEM_BYTES (SMEM_FLOATS*4)         // 110736 -> 2 CTAs/SM

// latent C region (selected LW2/Lb2) lives at wb[5504..5767] — inside the node
// Wf slot, which is only (re)written after latfinal when C is dead.
#define LC_W 5504
#define LC_B 5764

typedef unsigned long long ull;

__device__ __forceinline__ ull bcast2(float x){ ull r; unsigned u=__float_as_uint(x);
  asm("mov.b64 %0,{%1,%1};":"=l"(r):"r"(u)); return r; }
__device__ __forceinline__ void fma2(ull &a, ull x, ull w){
  asm("fma.rn.f32x2 %0,%1,%2,%0;":"+l"(a):"l"(x),"l"(w)); }
__device__ __forceinline__ float2 unpk(ull a){ unsigned x,y;
  asm("mov.b64 {%0,%1},%2;":"=r"(x),"=r"(y):"l"(a));
  return make_float2(__uint_as_float(x),__uint_as_float(y)); }

__device__ __forceinline__ unsigned smaddr(const void* p){
  return (unsigned)__cvta_generic_to_shared(p); }
__device__ __forceinline__ void cpa16(unsigned s, const void* g){
  asm volatile("cp.async.cg.shared.global [%0],[%1],16;\n"::"r"(s),"l"(g)); }
__device__ __forceinline__ void cpa8(unsigned s, const void* g){
  asm volatile("cp.async.ca.shared.global [%0],[%1],8;\n"::"r"(s),"l"(g)); }
__device__ __forceinline__ void cpcommit(){ asm volatile("cp.async.commit_group;"); }
template<int N> __device__ __forceinline__ void cpwait(){
  asm volatile("cp.async.wait_group %0;"::"n"(N)); }

// async-copy n4 float4s, all threads strided
__device__ __forceinline__ void agrp(float* dst, const float* __restrict__ src, int n4, int tid){
  for(int i=tid;i<n4;i+=NBLK) cpa16(smaddr(dst+4*i), src+4*i);
}

// IN inputs (stage rows R0..) -> 64 relu outputs (stage rows ORow..).
// Lane owns outs {og*4..+3} U {32+og*4..+3} for 8 elements at e8.
template<int IN, int R0, int ORow>
__device__ __forceinline__ void layer64(float* __restrict__ stg,
                                        const float* __restrict__ W,     // stride 64
                                        const float* __restrict__ bias,
                                        int og, int e8){
  ull acc[4][8];
  {
    const ull* bA=(const ull*)(bias + og*4);
    const ull* bB=(const ull*)(bias + 32 + og*4);
    ull b0=bA[0], b1=bA[1], b2=bB[0], b3=bB[1];
#pragma unroll
    for(int e=0;e<8;e++){acc[0][e]=b0;acc[1][e]=b1;acc[2][e]=b2;acc[3][e]=b3;}
  }
  const float* wA=W + og*4;
  const float* wB=W + 32 + og*4;
#pragma unroll 4
  for(int i=0;i<IN;i++){
    const float* xr = stg + SROW(R0+i) + e8;
    float4 ha=*(const float4*)(xr);
    float4 hb=*(const float4*)(xr+4);
    ulonglong2 wa=*(const ulonglong2*)(wA + i*64);
    ulonglong2 wc=*(const ulonglong2*)(wB + i*64);
    ull x[8]={bcast2(ha.x),bcast2(ha.y),bcast2(ha.z),bcast2(ha.w),
              bcast2(hb.x),bcast2(hb.y),bcast2(hb.z),bcast2(hb.w)};
#pragma unroll
    for(int e=0;e<8;e++){
      fma2(acc[0][e],x[e],wa.x); fma2(acc[1][e],x[e],wa.y);
      fma2(acc[2][e],x[e],wc.x); fma2(acc[3][e],x[e],wc.y);
    }
  }
#pragma unroll
  for(int c=0;c<2;c++){
#pragma unroll
    for(int p=0;p<2;p++){
      int pi=c*2+p;
      int r = ORow + c*32 + og*4 + 2*p;
      float lo[8], hi[8];
#pragma unroll
      for(int e=0;e<8;e++){
        float2 f=unpk(acc[pi][e]);
        lo[e]=fmaxf(f.x,0.f); hi[e]=fmaxf(f.y,0.f);
      }
      float* o0 = stg + SROW(r) + e8;
      float* o1 = stg + SROW(r+1) + e8;
      *(float4*)(o0)   = make_float4(lo[0],lo[1],lo[2],lo[3]);
      *(float4*)(o0+4) = make_float4(lo[4],lo[5],lo[6],lo[7]);
      *(float4*)(o1)   = make_float4(hi[0],hi[1],hi[2],hi[3]);
      *(float4*)(o1+4) = make_float4(hi[4],hi[5],hi[6],hi[7]);
    }
  }
}

__global__ __launch_bounds__(NBLK,2)
void gen_kernel(const float *__restrict__ z, const float *__restrict__ data,
                const float *__restrict__ glog, const float *__restrict__ glat,
                const float *__restrict__ gbin,
                const float *__restrict__ LW0, const float *__restrict__ Lb0,
                const float *__restrict__ LW1, const float *__restrict__ Lb1,
                const float *__restrict__ LW2, const float *__restrict__ Lb2,
                const float *__restrict__ NW0, const float *__restrict__ Nb0,
                const float *__restrict__ NW1, const float *__restrict__ Nb1,
                const float *__restrict__ NWf, const float *__restrict__ Nbf,
                const float *__restrict__ W7f, const float *__restrict__ b7f,
                float *__restrict__ out) {
  extern __shared__ float sm[];
  float* wb  = sm;
  float* STG = sm + STG_OFF;
  float* WST = sm + WST_OFF;
  const int tid=threadIdx.x;
  const int w=tid>>5, lane=tid&31;
  const int og=lane&7, eg=lane>>3;
  const int e8=w*32+eg*8;
  const int base=blockIdx.x*BE;

  __shared__ int ksel[4];
  if(tid<4){
    const float* a=glog+tid*8; const float* g=glat+tid*8;
    float best=a[0]+g[0]; int bi=0;
#pragma unroll
    for(int k=1;k<8;k++){ float v=a[k]+g[k]; if(v>best){best=v;bi=k;} } // first-max wins
    ksel[tid]=bi;
  }

  // ---- commit A0 (LW0/Lb0 l=0) and B0 (LW1/Lb1 l=0): no ksel dependency
  agrp(wb,      LW0, 128, tid); agrp(wb+512,  Lb0, 16, tid); cpcommit();
  agrp(wb+576,  LW1,1024, tid); agrp(wb+4672, Lb1, 16, tid); cpcommit();

  // data passthrough (cols 0..31) + var0 -> X rows 4..19 ; thread = element
  {
    int el=base+tid;
    const float* dr=data+(size_t)el*113;
    float* orw=out+(size_t)el*113;
#pragma unroll
    for(int c=0;c<16;c++){
      float v=dr[c]; orw[c]=v;
      STG[SROW(XROW+4+c)+tid]=v;
    }
#pragma unroll
    for(int c=16;c<32;c++) orw[c]=dr[c];
  }
  // z prefetch for l=0
  float4 zr0=*(const float4*)(z+(size_t)(base+tid)*32);
  float4 zr1=*(const float4*)(z+(size_t)(base+tid)*32+4);
  __syncthreads();   // ksel visible

  // ---- commit C0 (selected LW2/Lb2 l=0) into LC region
  {
    int k=ksel[0];
    if(tid<64) cpa16(smaddr(wb+LC_W+4*tid), LW2+((size_t)tid)*32+k*4);
    if(tid==64) cpa16(smaddr(wb+LC_B), Lb2+k*4);
    cpcommit();
  }

  // ================= latent phase =================
#pragma unroll 1
  for(int l=0;l<4;l++){
    { // stage z (regs) -> H2 rows 0..7
      STG[SROW(H2ROW+0)+tid]=zr0.x; STG[SROW(H2ROW+1)+tid]=zr0.y;
      STG[SROW(H2ROW+2)+tid]=zr0.z; STG[SROW(H2ROW+3)+tid]=zr0.w;
      STG[SROW(H2ROW+4)+tid]=zr1.x; STG[SROW(H2ROW+5)+tid]=zr1.y;
      STG[SROW(H2ROW+6)+tid]=zr1.z; STG[SROW(H2ROW+7)+tid]=zr1.w;
    }
    if(l<3){ // prefetch z for l+1 (covered by whole phase)
      zr0=*(const float4*)(z+(size_t)(base+tid)*32+(l+1)*8);
      zr1=*(const float4*)(z+(size_t)(base+tid)*32+(l+1)*8+4);
    }
    cpwait<2>(); __syncthreads();              // A_l ready (+z staged)
    layer64<8,  H2ROW, H1ROW>(STG, wb,     wb+512,  og, e8);
    __syncthreads();                           // W0 region wb[0..575] free
    if(l<3){ agrp(wb,LW0+(size_t)(l+1)*512,128,tid); agrp(wb+512,Lb0+(l+1)*64,16,tid); }
    else   { agrp(wb,NW0,144,tid); }           // node A part1: NW0[0..575] only (fits freed region)
    cpcommit();
    cpwait<2>(); __syncthreads();              // B_l ready
    layer64<64, H1ROW, H2ROW>(STG, wb+576, wb+4672, og, e8);
    __syncthreads();                           // W1 region wb[576..4735] free
    if(l<3){ agrp(wb+576,LW1+(size_t)(l+1)*4096,1024,tid); agrp(wb+4672,Lb1+(l+1)*64,16,tid); }
    else   { // node A part2 + node B (all inside freed wb[576..5503]; LC at 5504+ untouched)
      agrp(wb+576, NW0+576, 176, tid);         // NW0[576..1279]
      agrp(wb+1280, Nb0, 16, tid);
      agrp(wb+1344, NW1, 1024, tid);
      agrp(wb+5440, Nb1, 16, tid);
    }
    cpcommit();
    cpwait<2>(); __syncthreads();              // C_l ready
    { // latent final 64->4 selected (no relu)
      int eg4=lane&3, ef=w*32+eg4*8;
      ull acc[2][8];
      { const ull* bb=(const ull*)(wb+LC_B);
        ull b0=bb[0], b1=bb[1];
#pragma unroll
        for(int e=0;e<8;e++){acc[0][e]=b0;acc[1][e]=b1;} }
#pragma unroll 4
      for(int i=0;i<64;i++){
        const float* xr=STG+SROW(H2ROW+i)+ef;
        float4 ha=*(const float4*)(xr);
        float4 hb=*(const float4*)(xr+4);
        ulonglong2 wv=*(const ulonglong2*)(wb+LC_W+i*4);
        ull x[8]={bcast2(ha.x),bcast2(ha.y),bcast2(ha.z),bcast2(ha.w),
                  bcast2(hb.x),bcast2(hb.y),bcast2(hb.z),bcast2(hb.w)};
#pragma unroll
        for(int e=0;e<8;e++){ fma2(acc[0][e],x[e],wv.x); fma2(acc[1][e],x[e],wv.y); }
      }
      if(lane<4){
        float q0[8],q1[8],q2[8],q3[8];
#pragma unroll
        for(int e=0;e<8;e++){
          float2 f0=unpk(acc[0][e]), f1=unpk(acc[1][e]);
          q0[e]=f0.x; q1[e]=f0.y; q2[e]=f1.x; q3[e]=f1.y;
        }
        float* w0=WST+(l*4+0)*128+ef; float* w1=WST+(l*4+1)*128+ef;
        float* w2=WST+(l*4+2)*128+ef; float* w3=WST+(l*4+3)*128+ef;
        *(float4*)(w0)=make_float4(q0[0],q0[1],q0[2],q0[3]); *(float4*)(w0+4)=make_float4(q0[4],q0[5],q0[6],q0[7]);
        *(float4*)(w1)=make_float4(q1[0],q1[1],q1[2],q1[3]); *(float4*)(w1+4)=make_float4(q1[4],q1[5],q1[6],q1[7]);
        *(float4*)(w2)=make_float4(q2[0],q2[1],q2[2],q2[3]); *(float4*)(w2+4)=make_float4(q2[4],q2[5],q2[6],q2[7]);
        *(float4*)(w3)=make_float4(q3[0],q3[1],q3[2],q3[3]); *(float4*)(w3+4)=make_float4(q3[4],q3[5],q3[6],q3[7]);
      }
    }
    __syncthreads();                           // LC region free
    if(l<3){
      int k=ksel[l+1];
      if(tid<64) cpa16(smaddr(wb+LC_W+4*tid), LW2+((size_t)((l+1)*64+tid))*32+k*4);
      if(tid==64) cpa16(smaddr(wb+LC_B), Lb2+(l+1)*32+k*4);
    } else {
      agrp(wb+5504,NWf,256,tid); agrp(wb+6528,Nbf,4,tid);   // node C0 (overwrites dead LC)
    }
    cpcommit();
  }

  // ================= node chain =================
  const int LAY[6]={0,1,2,3,0,1};   // PARENT_LAT - 1
#pragma unroll 1
  for(int j=0;j<6;j++){
    { // lat features -> X rows 0..3
      const float* src=WST+LAY[j]*4*128+tid;
      STG[SROW(XROW+0)+tid]=src[0];
      STG[SROW(XROW+1)+tid]=src[128];
      STG[SROW(XROW+2)+tid]=src[256];
      STG[SROW(XROW+3)+tid]=src[384];
    }
    // j==0: NW0 was split across commits 1+2 -> drain both (wait<1>); else standard
    if(j==0) cpwait<1>(); else cpwait<2>();
    __syncthreads();                           // A_j ready (+X staged)
    layer64<20, XROW,  H1ROW>(STG, wb,      wb+1280, og, e8);
    __syncthreads();                           // W0 free
    if(j<5){ agrp(wb,NW0+(size_t)(j+1)*1280,320,tid); agrp(wb+1280,Nb0+(j+1)*64,16,tid); cpcommit(); }
    if(j<5) cpwait<2>(); else cpwait<1>();
    __syncthreads();                           // B_j ready
    layer64<64, H1ROW, H2ROW>(STG, wb+1344, wb+5440, og, e8);
    __syncthreads();                           // W1 free
    if(j<5){ agrp(wb+1344,NW1+(size_t)(j+1)*4096,1024,tid); agrp(wb+5440,Nb1+(j+1)*64,16,tid); cpcommit(); }
    if(j<5) cpwait<2>(); else cpwait<0>();
    __syncthreads();                           // C_j ready
    if(j<5){
      // node final 64->16 (no relu)
      int og2=lane&3, eg8=lane>>2, e4=w*32+eg8*4;
      ull acc[2][4];
      { const ull* bb=(const ull*)(wb+6528+og2*4);
        ull b0=bb[0], b1=bb[1];
#pragma unroll
        for(int e=0;e<4;e++){acc[0][e]=b0;acc[1][e]=b1;} }
#pragma unroll 4
      for(int i=0;i<64;i++){
        float4 h=*(const float4*)(STG+SROW(H2ROW+i)+e4);
        ulonglong2 wv=*(const ulonglong2*)(wb+5504+i*16+og2*4);
        ull x[4]={bcast2(h.x),bcast2(h.y),bcast2(h.z),bcast2(h.w)};
#pragma unroll
        for(int e=0;e<4;e++){ fma2(acc[0][e],x[e],wv.x); fma2(acc[1][e],x[e],wv.y); }
      }
      float v[4][4];
#pragma unroll
      for(int e=0;e<4;e++){
        float2 f0=unpk(acc[0][e]), f1=unpk(acc[1][e]);
        v[0][e]=f0.x; v[1][e]=f0.y; v[2][e]=f1.x; v[3][e]=f1.y;
      }
      int node=j+2;
#pragma unroll
      for(int q=0;q<4;q++){
        int o=og2*4+q;
        *(float4*)(STG+SROW(XROW+4+o)+e4)=make_float4(v[q][0],v[q][1],v[q][2],v[q][3]);
#pragma unroll
        for(int e=0;e<4;e++)
          out[(size_t)(base+e4+e)*113 + 16*node + o]=v[q][e];
      }
    } else {
      // node 7: 64->2 logits, sigmoid + gumbel hard argmax -> col 112
      int eg4=lane&3, ef=w*32+eg4*8;
      ull acc[8];
      { ull b=((const ull*)(wb+6528))[0];
#pragma unroll
        for(int e=0;e<8;e++) acc[e]=b; }
#pragma unroll 4
      for(int i=0;i<64;i++){
        const float* xr=STG+SROW(H2ROW+i)+ef;
        float4 ha=*(const float4*)(xr);
        float4 hb=*(const float4*)(xr+4);
        ull wv=*(const ull*)(wb+5504+i*2);
        fma2(acc[0],bcast2(ha.x),wv); fma2(acc[1],bcast2(ha.y),wv);
        fma2(acc[2],bcast2(ha.z),wv); fma2(acc[3],bcast2(ha.w),wv);
        fma2(acc[4],bcast2(hb.x),wv); fma2(acc[5],bcast2(hb.y),wv);
        fma2(acc[6],bcast2(hb.z),wv); fma2(acc[7],bcast2(hb.w),wv);
      }
      if(lane<4){
#pragma unroll
        for(int e=0;e<8;e++){
          float2 f=unpk(acc[e]);
          float p0=1.f/(1.f+expf(-f.x));
          float p1=1.f/(1.f+expf(-f.y));
          int el=base+ef+e;
          float g0=gbin[(size_t)el*2], g1=gbin[(size_t)el*2+1];
          out[(size_t)el*113+112]=(p0+g0>=p1+g1)?1.f:0.f;   // first-index wins ties
        }
      }
    }
    __syncthreads();                           // Wf region free
    if(j<5){
      if(j<4){ agrp(wb+5504,NWf+(size_t)(j+1)*1024,256,tid); agrp(wb+6528,Nbf+(j+1)*16,4,tid); }
      else   { if(tid<32) cpa16(smaddr(wb+5504+4*tid), W7f+4*tid);
               if(tid==32) cpa8(smaddr(wb+6528), b7f); }
      cpcommit();
    }
  }
}

extern "C" void kernel_launch(void *const *d_in, const int *in_sizes, int n_in,
                              void *d_out, int out_size) {
  (void)in_sizes; (void)n_in; (void)out_size;
  const float *z    = (const float *)d_in[0];
  const float *data = (const float *)d_in[1];
  const float *glog = (const float *)d_in[2];
  const float *glat = (const float *)d_in[3];
  const float *gbin = (const float *)d_in[4];
  const float *LW0  = (const float *)d_in[5];
  const float *Lb0  = (const float *)d_in[6];
  const float *LW1  = (const float *)d_in[7];
  const float *Lb1  = (const float *)d_in[8];
  const float *LW2  = (const float *)d_in[9];
  const float *Lb2  = (const float *)d_in[10];
  const float *NW0  = (const float *)d_in[11];
  const float *Nb0  = (const float *)d_in[12];
  const float *NW1  = (const float *)d_in[13];
  const float *Nb1  = (const float *)d_in[14];
  const float *NWf  = (const float *)d_in[15];
  const float *Nbf  = (const float *)d_in[16];
  const float *W7f  = (const float *)d_in[17];
  const float *b7f  = (const float *)d_in[18];
  float *out = (float *)d_out;

  cudaFuncSetAttribute(gen_kernel, cudaFuncAttributeMaxDynamicSharedMemorySize, SMEM_BYTES);
  gen_kernel<<<131072/BE, NBLK, SMEM_BYTES>>>(
      z, data, glog, glat, gbin, LW0, Lb0, LW1, Lb1, LW2, Lb2,
      NW0, Nb0, NW1, Nb1, NWf, Nbf, W7f, b7f, out);
}